// round 1
// baseline (speedup 1.0000x reference)
#include <cuda_runtime.h>
#include <cuda_bf16.h>
#include <math.h>

// Problem constants
#define S_LEN 4096
#define D_MODEL 1024
#define NUM_HEADS 16
#define DK 64
#define NUM_BUCKETS 32

// Scratch (device globals: no allocation allowed)
__device__ float g_Q[NUM_HEADS * S_LEN * DK];
__device__ float g_K[NUM_HEADS * S_LEN * DK];
__device__ float g_V[NUM_HEADS * S_LEN * DK];
__device__ float g_ctx[S_LEN * D_MODEL];
__device__ float g_bias[NUM_HEADS * S_LEN];   // bias per (head, distance n = q-k >= 0)

// ---------------------------------------------------------------------------
// Bias table: T5 relative position bucket (unidirectional), fp32 to match ref
// ---------------------------------------------------------------------------
__global__ void bias_table_kernel(const float* __restrict__ rpe) {
    int idx = blockIdx.x * blockDim.x + threadIdx.x;
    if (idx >= NUM_HEADS * S_LEN) return;
    int h = idx / S_LEN;
    int n = idx % S_LEN;   // distance q-k, >= 0
    int bucket;
    if (n < 16) {
        bucket = n;
    } else {
        // match jnp fp32 ops: log(n/16) / log(256) * 16, truncate
        float t = logf((float)n * 0.0625f);
        float v = t / 5.545177444479562f;
        v = v * 16.0f;
        bucket = 16 + (int)v;
        if (bucket > NUM_BUCKETS - 1) bucket = NUM_BUCKETS - 1;
    }
    g_bias[h * S_LEN + n] = rpe[bucket * NUM_HEADS + h];
}

// ---------------------------------------------------------------------------
// GEMM: Y[M=4096, N=1024] = X[4096,1024] @ W[1024,1024] + b
// BM=BN=64, BK=16, 256 threads, 4x4 microtile.
// HEAD_SCATTER: write Y into [H][S][DK] layout instead of [S][D].
// ---------------------------------------------------------------------------
template <bool HEAD_SCATTER>
__global__ __launch_bounds__(256) void gemm_kernel(
    const float* __restrict__ X, const float* __restrict__ W,
    const float* __restrict__ b, float* __restrict__ Y)
{
    __shared__ float Xs[16][64];   // [k][m]
    __shared__ float Ws[16][64];   // [k][n]

    const int bn = blockIdx.x, bm = blockIdx.y;
    const int row0 = bm * 64, col0 = bn * 64;
    const int tid = threadIdx.x;
    const int tx = tid & 15, ty = tid >> 4;

    float acc[4][4];
#pragma unroll
    for (int i = 0; i < 4; i++)
#pragma unroll
        for (int j = 0; j < 4; j++) acc[i][j] = 0.f;

    const int xr = tid >> 2, xc4 = (tid & 3) * 4;
    const int wr = tid >> 4, wc4 = (tid & 15) * 4;

    for (int kk = 0; kk < D_MODEL; kk += 16) {
        float4 xv = *(const float4*)&X[(row0 + xr) * D_MODEL + kk + xc4];
        Xs[xc4 + 0][xr] = xv.x;
        Xs[xc4 + 1][xr] = xv.y;
        Xs[xc4 + 2][xr] = xv.z;
        Xs[xc4 + 3][xr] = xv.w;
        float4 wv = *(const float4*)&W[(kk + wr) * D_MODEL + col0 + wc4];
        *(float4*)&Ws[wr][wc4] = wv;
        __syncthreads();

#pragma unroll
        for (int k = 0; k < 16; k++) {
            float4 a = *(const float4*)&Xs[k][ty * 4];
            float4 bb = *(const float4*)&Ws[k][tx * 4];
            float av[4] = {a.x, a.y, a.z, a.w};
            float bv[4] = {bb.x, bb.y, bb.z, bb.w};
#pragma unroll
            for (int i = 0; i < 4; i++)
#pragma unroll
                for (int j = 0; j < 4; j++) acc[i][j] += av[i] * bv[j];
        }
        __syncthreads();
    }

#pragma unroll
    for (int i = 0; i < 4; i++) {
        int row = row0 + ty * 4 + i;
#pragma unroll
        for (int j = 0; j < 4; j++) {
            int col = col0 + tx * 4 + j;
            float val = acc[i][j] + b[col];
            if (HEAD_SCATTER) {
                // [H][S][DK]
                Y[(col >> 6) * (S_LEN * DK) + row * DK + (col & 63)] = val;
            } else {
                Y[row * D_MODEL + col] = val;
            }
        }
    }
}

// ---------------------------------------------------------------------------
// Flash attention, causal, with relative-position bias.
// Grid: (64 q-tiles, 16 heads). Block: 256 threads.
// Thread layout: r = tid>>2 (query row in tile), quad = tid&3.
// Each thread owns 16 score columns (k positions) and accumulates a partial
// O[64]; quad-reduced at the end via shuffles.
// ---------------------------------------------------------------------------
#define SMEM_FLOATS (3 * 64 * 64 + 128)

__global__ __launch_bounds__(256, 2) void flash_kernel(float* __restrict__ ctx)
{
    extern __shared__ float sm[];
    float* Qs = sm;                 // 64x64
    float* Ks = sm + 4096;          // 64x64
    float* Vs = sm + 8192;          // 64x64
    float* sbias = sm + 12288;      // 128

    const int qt = (gridDim.x - 1) - blockIdx.x;   // biggest tiles scheduled first
    const int h = blockIdx.y;
    const int qbase = qt * 64;
    const int tid = threadIdx.x;
    const int r = tid >> 2;
    const int quad = tid & 3;
    const int cb = quad * 16;   // score-column base for this thread

    const float* Qg = g_Q + (size_t)h * S_LEN * DK + (size_t)qbase * DK;
    const float* Kg = g_K + (size_t)h * S_LEN * DK;
    const float* Vg = g_V + (size_t)h * S_LEN * DK;

    // Load Q tile
#pragma unroll
    for (int i = 0; i < 4; i++)
        ((float4*)Qs)[tid + i * 256] = ((const float4*)Qg)[tid + i * 256];

    float m = -INFINITY;
    float l = 0.f;
    float O[64];
#pragma unroll
    for (int c = 0; c < 64; c++) O[c] = 0.f;

    for (int kt = 0; kt <= qt; kt++) {
        const int kbase = kt * 64;
        const int d0 = qbase - kbase;

        __syncthreads();   // previous iteration readers done
        const float4* Kg4 = (const float4*)(Kg + (size_t)kbase * DK);
        const float4* Vg4 = (const float4*)(Vg + (size_t)kbase * DK);
#pragma unroll
        for (int i = 0; i < 4; i++) {
            ((float4*)Ks)[tid + i * 256] = Kg4[tid + i * 256];
            ((float4*)Vs)[tid + i * 256] = Vg4[tid + i * 256];
        }
        if (tid < 128) {
            int delta = d0 - 63 + tid;
            sbias[tid] = (delta >= 0 && delta < S_LEN) ? g_bias[h * S_LEN + delta] : 0.f;
        }
        __syncthreads();

        // ---- scores: s[j] = Q[r] . K[cb+j] ----
        float s[16];
#pragma unroll
        for (int j = 0; j < 16; j++) s[j] = 0.f;
        const float4* q4 = (const float4*)(Qs + r * DK);
#pragma unroll
        for (int d4 = 0; d4 < 16; d4++) {
            float4 q = q4[d4];
#pragma unroll
            for (int j = 0; j < 16; j++) {
                float4 k = ((const float4*)(Ks + (cb + j) * DK))[d4];
                s[j] += q.x * k.x + q.y * k.y + q.z * k.z + q.w * k.w;
            }
        }

        // ---- scale + bias + causal mask ----
#pragma unroll
        for (int j = 0; j < 16; j++) {
            int jj = cb + j;
            int delta = d0 + r - jj;
            if (delta >= 0)
                s[j] = s[j] * 0.125f + sbias[r - jj + 63];
            else
                s[j] = -1e30f;
        }

        // ---- online softmax update (row = 4 lanes: quad group) ----
        float mt = -INFINITY;
#pragma unroll
        for (int j = 0; j < 16; j++) mt = fmaxf(mt, s[j]);
        mt = fmaxf(mt, __shfl_xor_sync(0xffffffffu, mt, 1));
        mt = fmaxf(mt, __shfl_xor_sync(0xffffffffu, mt, 2));
        float mnew = fmaxf(m, mt);
        float corr = __expf(m - mnew);
        float lsum = 0.f;
#pragma unroll
        for (int j = 0; j < 16; j++) {
            float p = __expf(s[j] - mnew);
            s[j] = p;
            lsum += p;
        }
        lsum += __shfl_xor_sync(0xffffffffu, lsum, 1);
        lsum += __shfl_xor_sync(0xffffffffu, lsum, 2);
        l = l * corr + lsum;
        m = mnew;
#pragma unroll
        for (int c = 0; c < 64; c++) O[c] *= corr;

        // ---- O += P @ V (partial over this thread's 16 k positions) ----
#pragma unroll
        for (int j = 0; j < 16; j++) {
            float pj = s[j];
            const float4* v4 = (const float4*)(Vs + (cb + j) * DK);
#pragma unroll
            for (int c4 = 0; c4 < 16; c4++) {
                float4 v = v4[c4];
                O[c4 * 4 + 0] += pj * v.x;
                O[c4 * 4 + 1] += pj * v.y;
                O[c4 * 4 + 2] += pj * v.z;
                O[c4 * 4 + 3] += pj * v.w;
            }
        }
    }

    // quad-reduce O, normalize, write
#pragma unroll
    for (int c = 0; c < 64; c++) {
        O[c] += __shfl_xor_sync(0xffffffffu, O[c], 1);
        O[c] += __shfl_xor_sync(0xffffffffu, O[c], 2);
    }
    float inv = 1.f / l;
    float* dst = ctx + (size_t)(qbase + r) * D_MODEL + h * DK + quad * 16;
#pragma unroll
    for (int c4 = 0; c4 < 4; c4++) {
        float4 o;
        o.x = O[quad * 16 + c4 * 4 + 0] * inv;
        o.y = O[quad * 16 + c4 * 4 + 1] * inv;
        o.z = O[quad * 16 + c4 * 4 + 2] * inv;
        o.w = O[quad * 16 + c4 * 4 + 3] * inv;
        *(float4*)(dst + c4 * 4) = o;
    }
}

// ---------------------------------------------------------------------------
extern "C" void kernel_launch(void* const* d_in, const int* in_sizes, int n_in,
                              void* d_out, int out_size)
{
    const float* query = (const float*)d_in[0];
    const float* key   = (const float*)d_in[1];
    const float* value = (const float*)d_in[2];
    // d_in[3] = mask (causal, known statically) -- ignored
    const float* Wq = (const float*)d_in[4];
    const float* bq = (const float*)d_in[5];
    const float* Wk = (const float*)d_in[6];
    const float* bk = (const float*)d_in[7];
    const float* Wv = (const float*)d_in[8];
    const float* bv = (const float*)d_in[9];
    const float* Wo = (const float*)d_in[10];
    const float* bo = (const float*)d_in[11];
    const float* rpe = (const float*)d_in[12];
    float* out = (float*)d_out;

    float *gQ, *gK, *gV, *gctx;
    cudaGetSymbolAddress((void**)&gQ, g_Q);
    cudaGetSymbolAddress((void**)&gK, g_K);
    cudaGetSymbolAddress((void**)&gV, g_V);
    cudaGetSymbolAddress((void**)&gctx, g_ctx);

    // bias table
    bias_table_kernel<<<(NUM_HEADS * S_LEN + 255) / 256, 256>>>(rpe);

    // projections -> [H][S][DK]
    dim3 ggrid(D_MODEL / 64, S_LEN / 64);
    gemm_kernel<true><<<ggrid, 256>>>(query, Wq, bq, gQ);
    gemm_kernel<true><<<ggrid, 256>>>(key,   Wk, bk, gK);
    gemm_kernel<true><<<ggrid, 256>>>(value, Wv, bv, gV);

    // flash attention
    static bool attr_set = false;
    size_t smem_bytes = SMEM_FLOATS * sizeof(float);
    cudaFuncSetAttribute(flash_kernel, cudaFuncAttributeMaxDynamicSharedMemorySize,
                         (int)smem_bytes);
    dim3 fgrid(S_LEN / 64, NUM_HEADS);
    flash_kernel<<<fgrid, 256, smem_bytes>>>(gctx);

    // output projection
    gemm_kernel<false><<<ggrid, 256>>>(gctx, Wo, bo, out);
    (void)attr_set; (void)in_sizes; (void)n_in; (void)out_size;
}

// round 2
// speedup vs baseline: 7.4148x; 7.4148x over previous
#include <cuda_runtime.h>
#include <cuda_bf16.h>
#include <math.h>

// Problem constants
#define S_LEN 4096
#define D_MODEL 1024
#define NUM_HEADS 16
#define DK 64
#define NUM_BUCKETS 32

// Scratch (device globals: no allocation allowed)
__device__ float g_Q[NUM_HEADS * S_LEN * DK];
__device__ float g_K[NUM_HEADS * S_LEN * DK];
__device__ float g_V[NUM_HEADS * S_LEN * DK];
__device__ float g_ctx[S_LEN * D_MODEL];
__device__ float g_bias[NUM_HEADS * S_LEN];   // bias per (head, distance n = q-k >= 0)

// ---------------------------------------------------------------------------
// tf32 helpers
// ---------------------------------------------------------------------------
__device__ __forceinline__ float tf32_round(float x) {
    unsigned u;
    asm("cvt.rna.tf32.f32 %0, %1;" : "=r"(u) : "f"(x));
    return __uint_as_float(u);
}

__device__ __forceinline__ void mma_tf32(float c[4],
                                         unsigned a0, unsigned a1, unsigned a2, unsigned a3,
                                         unsigned b0, unsigned b1) {
    asm volatile(
        "mma.sync.aligned.m16n8k8.row.col.f32.tf32.tf32.f32 "
        "{%0,%1,%2,%3}, {%4,%5,%6,%7}, {%8,%9}, {%0,%1,%2,%3};"
        : "+f"(c[0]), "+f"(c[1]), "+f"(c[2]), "+f"(c[3])
        : "r"(a0), "r"(a1), "r"(a2), "r"(a3), "r"(b0), "r"(b1));
}

// ---------------------------------------------------------------------------
// Bias table: T5 relative position bucket (unidirectional), fp32 to match ref
// ---------------------------------------------------------------------------
__global__ void bias_table_kernel(const float* __restrict__ rpe) {
    int idx = blockIdx.x * blockDim.x + threadIdx.x;
    if (idx >= NUM_HEADS * S_LEN) return;
    int h = idx / S_LEN;
    int n = idx % S_LEN;   // distance q-k, >= 0
    int bucket;
    if (n < 16) {
        bucket = n;
    } else {
        float t = logf((float)n * 0.0625f);
        float v = t / 5.545177444479562f;
        v = v * 16.0f;
        bucket = 16 + (int)v;
        if (bucket > NUM_BUCKETS - 1) bucket = NUM_BUCKETS - 1;
    }
    g_bias[h * S_LEN + n] = rpe[bucket * NUM_HEADS + h];
}

// ---------------------------------------------------------------------------
// GEMM: Y[M=4096, N=1024] = X[4096,1024] @ W[1024,1024] + b  (fp32 FFMA)
// HEAD_SCATTER: write Y into [H][S][DK] layout, tf32-rounded (feeds MMA attn).
// ---------------------------------------------------------------------------
template <bool HEAD_SCATTER>
__global__ __launch_bounds__(256) void gemm_kernel(
    const float* __restrict__ X, const float* __restrict__ W,
    const float* __restrict__ b, float* __restrict__ Y)
{
    __shared__ float Xs[16][64];   // [k][m]
    __shared__ float Ws[16][64];   // [k][n]

    const int bn = blockIdx.x, bm = blockIdx.y;
    const int row0 = bm * 64, col0 = bn * 64;
    const int tid = threadIdx.x;
    const int tx = tid & 15, ty = tid >> 4;

    float acc[4][4];
#pragma unroll
    for (int i = 0; i < 4; i++)
#pragma unroll
        for (int j = 0; j < 4; j++) acc[i][j] = 0.f;

    const int xr = tid >> 2, xc4 = (tid & 3) * 4;
    const int wr = tid >> 4, wc4 = (tid & 15) * 4;

    for (int kk = 0; kk < D_MODEL; kk += 16) {
        float4 xv = *(const float4*)&X[(row0 + xr) * D_MODEL + kk + xc4];
        Xs[xc4 + 0][xr] = xv.x;
        Xs[xc4 + 1][xr] = xv.y;
        Xs[xc4 + 2][xr] = xv.z;
        Xs[xc4 + 3][xr] = xv.w;
        float4 wv = *(const float4*)&W[(kk + wr) * D_MODEL + col0 + wc4];
        *(float4*)&Ws[wr][wc4] = wv;
        __syncthreads();

#pragma unroll
        for (int k = 0; k < 16; k++) {
            float4 a = *(const float4*)&Xs[k][ty * 4];
            float4 bb = *(const float4*)&Ws[k][tx * 4];
            float av[4] = {a.x, a.y, a.z, a.w};
            float bv[4] = {bb.x, bb.y, bb.z, bb.w};
#pragma unroll
            for (int i = 0; i < 4; i++)
#pragma unroll
                for (int j = 0; j < 4; j++) acc[i][j] += av[i] * bv[j];
        }
        __syncthreads();
    }

#pragma unroll
    for (int i = 0; i < 4; i++) {
        int row = row0 + ty * 4 + i;
#pragma unroll
        for (int j = 0; j < 4; j++) {
            int col = col0 + tx * 4 + j;
            float val = acc[i][j] + b[col];
            if (HEAD_SCATTER) {
                // [H][S][DK], tf32-rounded for the MMA attention kernel
                Y[(col >> 6) * (S_LEN * DK) + row * DK + (col & 63)] = tf32_round(val);
            } else {
                Y[row * D_MODEL + col] = val;
            }
        }
    }
}

// ---------------------------------------------------------------------------
// Flash attention with mma.sync.m16n8k8.tf32.
// Grid: (64 q-tiles of 64 rows, 16 heads). Block: 128 threads = 4 warps.
// Warp w owns q rows [qbase + 16w, qbase + 16w + 16).
// Q fragments register-resident across all k-tiles. K/V/P staged in smem with
// padded strides (68 / 72 / 68 floats) for conflict-free fragment loads.
// ---------------------------------------------------------------------------
#define KS_OFF 0
#define VS_OFF (64 * 68)               // 4352
#define PS_OFF (VS_OFF + 64 * 72)      // 8960
#define SB_OFF (PS_OFF + 64 * 68)      // 13312
#define FM_FLOATS (SB_OFF + 128)       // 13440 floats = 53760 B

__global__ __launch_bounds__(128) void flash_mma_kernel(float* __restrict__ ctx)
{
    extern __shared__ float sm[];
    float* Ks = sm + KS_OFF;
    float* Vs = sm + VS_OFF;
    float* Ps = sm + PS_OFF;
    float* sbias = sm + SB_OFF;

    const int qt = (int)gridDim.x - 1 - (int)blockIdx.x;  // biggest tiles first
    const int h = blockIdx.y;
    const int qbase = qt * 64;
    const int tid = threadIdx.x;
    const int lane = tid & 31;
    const int w = tid >> 5;
    const int g = lane >> 2;       // group id (row within fragment)
    const int tig = lane & 3;      // thread in group
    const int wrow = w * 16;       // warp's row offset within q-tile
    const int r0 = wrow + g;       // this thread's first q row (tile-relative)
    const int r1 = r0 + 8;         // second q row

    const float* Qg = g_Q + ((size_t)h * S_LEN + qbase + wrow) * DK;
    const float4* Kg4 = (const float4*)(g_K + (size_t)h * S_LEN * DK);
    const float4* Vg4 = (const float4*)(g_V + (size_t)h * S_LEN * DK);

    // Q fragments (tf32 bits), 8 k-chunks x 4 regs
    unsigned qa[8][4];
#pragma unroll
    for (int kc = 0; kc < 8; kc++) {
        qa[kc][0] = __float_as_uint(Qg[g       * DK + kc * 8 + tig]);
        qa[kc][1] = __float_as_uint(Qg[(g + 8) * DK + kc * 8 + tig]);
        qa[kc][2] = __float_as_uint(Qg[g       * DK + kc * 8 + tig + 4]);
        qa[kc][3] = __float_as_uint(Qg[(g + 8) * DK + kc * 8 + tig + 4]);
    }

    float O[8][4];
#pragma unroll
    for (int db = 0; db < 8; db++)
#pragma unroll
        for (int c = 0; c < 4; c++) O[db][c] = 0.f;

    float m0 = -INFINITY, m1 = -INFINITY, l0 = 0.f, l1 = 0.f;

    for (int kt = 0; kt <= qt; kt++) {
        const int kbase = kt * 64;
        const int d0 = qbase - kbase;

        __syncthreads();   // previous iteration's readers done
#pragma unroll
        for (int i = 0; i < 8; i++) {
            int idx = tid + i * 128;
            int key = idx >> 4, d4 = idx & 15;
            float4 kv = Kg4[kbase * 16 + idx];
            float4 vv = Vg4[kbase * 16 + idx];
            *(float4*)&Ks[key * 68 + d4 * 4] = kv;
            *(float4*)&Vs[key * 72 + d4 * 4] = vv;
        }
        if (tid < 127) {
            int delta = d0 - 63 + tid;
            sbias[tid] = (delta >= 0) ? g_bias[h * S_LEN + delta] : 0.f;
        }
        __syncthreads();

        // Warp entirely above the causal diagonal for this k-tile -> skip
        if (kbase > qbase + wrow + 15) continue;

        // ---- S = Q @ K^T (16 x 64 per warp) ----
        float Sc[8][4];
#pragma unroll
        for (int nb = 0; nb < 8; nb++)
#pragma unroll
            for (int c = 0; c < 4; c++) Sc[nb][c] = 0.f;

#pragma unroll
        for (int kc = 0; kc < 8; kc++) {
#pragma unroll
            for (int nb = 0; nb < 8; nb++) {
                unsigned b0 = __float_as_uint(Ks[(nb * 8 + g) * 68 + kc * 8 + tig]);
                unsigned b1 = __float_as_uint(Ks[(nb * 8 + g) * 68 + kc * 8 + tig + 4]);
                mma_tf32(Sc[nb], qa[kc][0], qa[kc][1], qa[kc][2], qa[kc][3], b0, b1);
            }
        }

        // ---- scale + bias + causal mask + running max ----
        float mt0 = -INFINITY, mt1 = -INFINITY;
#pragma unroll
        for (int nb = 0; nb < 8; nb++) {
            int col0 = nb * 8 + 2 * tig;
            float v00 = Sc[nb][0] * 0.125f + sbias[r0 - col0 + 63];
            float v01 = Sc[nb][1] * 0.125f + sbias[r0 - col0 + 62];
            float v10 = Sc[nb][2] * 0.125f + sbias[r1 - col0 + 63];
            float v11 = Sc[nb][3] * 0.125f + sbias[r1 - col0 + 62];
            Sc[nb][0] = (d0 + r0 - col0     >= 0) ? v00 : -1e30f;
            Sc[nb][1] = (d0 + r0 - col0 - 1 >= 0) ? v01 : -1e30f;
            Sc[nb][2] = (d0 + r1 - col0     >= 0) ? v10 : -1e30f;
            Sc[nb][3] = (d0 + r1 - col0 - 1 >= 0) ? v11 : -1e30f;
            mt0 = fmaxf(mt0, fmaxf(Sc[nb][0], Sc[nb][1]));
            mt1 = fmaxf(mt1, fmaxf(Sc[nb][2], Sc[nb][3]));
        }
        mt0 = fmaxf(mt0, __shfl_xor_sync(0xffffffffu, mt0, 1));
        mt0 = fmaxf(mt0, __shfl_xor_sync(0xffffffffu, mt0, 2));
        mt1 = fmaxf(mt1, __shfl_xor_sync(0xffffffffu, mt1, 1));
        mt1 = fmaxf(mt1, __shfl_xor_sync(0xffffffffu, mt1, 2));

        float mn0 = fmaxf(m0, mt0), mn1 = fmaxf(m1, mt1);
        float corr0 = __expf(m0 - mn0), corr1 = __expf(m1 - mn1);
        float ls0 = 0.f, ls1 = 0.f;
#pragma unroll
        for (int nb = 0; nb < 8; nb++) {
            Sc[nb][0] = __expf(Sc[nb][0] - mn0);
            Sc[nb][1] = __expf(Sc[nb][1] - mn0);
            Sc[nb][2] = __expf(Sc[nb][2] - mn1);
            Sc[nb][3] = __expf(Sc[nb][3] - mn1);
            ls0 += Sc[nb][0] + Sc[nb][1];
            ls1 += Sc[nb][2] + Sc[nb][3];
        }
        ls0 += __shfl_xor_sync(0xffffffffu, ls0, 1);
        ls0 += __shfl_xor_sync(0xffffffffu, ls0, 2);
        ls1 += __shfl_xor_sync(0xffffffffu, ls1, 1);
        ls1 += __shfl_xor_sync(0xffffffffu, ls1, 2);
        l0 = l0 * corr0 + ls0;  m0 = mn0;
        l1 = l1 * corr1 + ls1;  m1 = mn1;

#pragma unroll
        for (int db = 0; db < 8; db++) {
            O[db][0] *= corr0; O[db][1] *= corr0;
            O[db][2] *= corr1; O[db][3] *= corr1;
        }

        // ---- stage P (tf32-rounded) into this warp's smem region ----
#pragma unroll
        for (int nb = 0; nb < 8; nb++) {
            int col0 = nb * 8 + 2 * tig;
            float2 p0 = make_float2(tf32_round(Sc[nb][0]), tf32_round(Sc[nb][1]));
            float2 p1 = make_float2(tf32_round(Sc[nb][2]), tf32_round(Sc[nb][3]));
            *(float2*)&Ps[r0 * 68 + col0] = p0;
            *(float2*)&Ps[r1 * 68 + col0] = p1;
        }
        __syncwarp();

        // ---- O += P @ V ----
#pragma unroll
        for (int kc2 = 0; kc2 < 8; kc2++) {
            unsigned pa0 = __float_as_uint(Ps[r0 * 68 + kc2 * 8 + tig]);
            unsigned pa1 = __float_as_uint(Ps[r1 * 68 + kc2 * 8 + tig]);
            unsigned pa2 = __float_as_uint(Ps[r0 * 68 + kc2 * 8 + tig + 4]);
            unsigned pa3 = __float_as_uint(Ps[r1 * 68 + kc2 * 8 + tig + 4]);
#pragma unroll
            for (int db = 0; db < 8; db++) {
                unsigned vb0 = __float_as_uint(Vs[(kc2 * 8 + tig)     * 72 + db * 8 + g]);
                unsigned vb1 = __float_as_uint(Vs[(kc2 * 8 + tig + 4) * 72 + db * 8 + g]);
                mma_tf32(O[db], pa0, pa1, pa2, pa3, vb0, vb1);
            }
        }
    }

    // ---- normalize + write ctx ----
    float inv0 = 1.f / l0, inv1 = 1.f / l1;
    float* dst0 = ctx + (size_t)(qbase + r0) * D_MODEL + h * DK;
    float* dst1 = ctx + (size_t)(qbase + r1) * D_MODEL + h * DK;
#pragma unroll
    for (int db = 0; db < 8; db++) {
        int col0 = db * 8 + 2 * tig;
        *(float2*)&dst0[col0] = make_float2(O[db][0] * inv0, O[db][1] * inv0);
        *(float2*)&dst1[col0] = make_float2(O[db][2] * inv1, O[db][3] * inv1);
    }
}

// ---------------------------------------------------------------------------
extern "C" void kernel_launch(void* const* d_in, const int* in_sizes, int n_in,
                              void* d_out, int out_size)
{
    const float* query = (const float*)d_in[0];
    const float* key   = (const float*)d_in[1];
    const float* value = (const float*)d_in[2];
    // d_in[3] = mask (causal, known statically) -- ignored
    const float* Wq = (const float*)d_in[4];
    const float* bq = (const float*)d_in[5];
    const float* Wk = (const float*)d_in[6];
    const float* bk = (const float*)d_in[7];
    const float* Wv = (const float*)d_in[8];
    const float* bv = (const float*)d_in[9];
    const float* Wo = (const float*)d_in[10];
    const float* bo = (const float*)d_in[11];
    const float* rpe = (const float*)d_in[12];
    float* out = (float*)d_out;

    float *gQ, *gK, *gV, *gctx;
    cudaGetSymbolAddress((void**)&gQ, g_Q);
    cudaGetSymbolAddress((void**)&gK, g_K);
    cudaGetSymbolAddress((void**)&gV, g_V);
    cudaGetSymbolAddress((void**)&gctx, g_ctx);

    // bias table
    bias_table_kernel<<<(NUM_HEADS * S_LEN + 255) / 256, 256>>>(rpe);

    // projections -> [H][S][DK], tf32-rounded
    dim3 ggrid(D_MODEL / 64, S_LEN / 64);
    gemm_kernel<true><<<ggrid, 256>>>(query, Wq, bq, gQ);
    gemm_kernel<true><<<ggrid, 256>>>(key,   Wk, bk, gK);
    gemm_kernel<true><<<ggrid, 256>>>(value, Wv, bv, gV);

    // flash attention (tensor-core tf32)
    size_t smem_bytes = FM_FLOATS * sizeof(float);
    cudaFuncSetAttribute(flash_mma_kernel, cudaFuncAttributeMaxDynamicSharedMemorySize,
                         (int)smem_bytes);
    dim3 fgrid(S_LEN / 64, NUM_HEADS);
    flash_mma_kernel<<<fgrid, 128, smem_bytes>>>(gctx);

    // output projection (fp32)
    gemm_kernel<false><<<ggrid, 256>>>(gctx, Wo, bo, out);
    (void)in_sizes; (void)n_in; (void)out_size;
}

// round 4
// speedup vs baseline: 13.1066x; 1.7676x over previous
#include <cuda_runtime.h>
#include <cuda_bf16.h>
#include <math.h>
#include <stdint.h>
#include <cstdint>

// Problem constants
#define S_LEN 4096
#define D_MODEL 1024
#define NUM_HEADS 16
#define DK 64
#define NUM_BUCKETS 32

// Scratch (device globals: no allocation allowed)
__device__ float g_Q[NUM_HEADS * S_LEN * DK];
__device__ float g_K[NUM_HEADS * S_LEN * DK];
__device__ float g_V[NUM_HEADS * S_LEN * DK];
__device__ float g_ctx[S_LEN * D_MODEL];
__device__ float g_bias[NUM_HEADS * S_LEN];

// bf16 split operands
__device__ __nv_bfloat16 g_XH[3 * S_LEN * D_MODEL];
__device__ __nv_bfloat16 g_XL[3 * S_LEN * D_MODEL];
__device__ __nv_bfloat16 g_CH[S_LEN * D_MODEL];
__device__ __nv_bfloat16 g_CL[S_LEN * D_MODEL];
__device__ __nv_bfloat16 g_WTH[4 * D_MODEL * D_MODEL];   // transposed [n][k]
__device__ __nv_bfloat16 g_WTL[4 * D_MODEL * D_MODEL];

// ---------------------------------------------------------------------------
// helpers
// ---------------------------------------------------------------------------
__device__ __forceinline__ float tf32_round(float x) {
    unsigned u;
    asm("cvt.rna.tf32.f32 %0, %1;" : "=r"(u) : "f"(x));
    return __uint_as_float(u);
}

__device__ __forceinline__ void mma_tf32(float c[4],
                                         unsigned a0, unsigned a1, unsigned a2, unsigned a3,
                                         unsigned b0, unsigned b1) {
    asm volatile(
        "mma.sync.aligned.m16n8k8.row.col.f32.tf32.tf32.f32 "
        "{%0,%1,%2,%3}, {%4,%5,%6,%7}, {%8,%9}, {%0,%1,%2,%3};"
        : "+f"(c[0]), "+f"(c[1]), "+f"(c[2]), "+f"(c[3])
        : "r"(a0), "r"(a1), "r"(a2), "r"(a3), "r"(b0), "r"(b1));
}

__device__ __forceinline__ void mma_bf16(float c[4],
                                         unsigned a0, unsigned a1, unsigned a2, unsigned a3,
                                         unsigned b0, unsigned b1) {
    asm volatile(
        "mma.sync.aligned.m16n8k16.row.col.f32.bf16.bf16.f32 "
        "{%0,%1,%2,%3}, {%4,%5,%6,%7}, {%8,%9}, {%0,%1,%2,%3};"
        : "+f"(c[0]), "+f"(c[1]), "+f"(c[2]), "+f"(c[3])
        : "r"(a0), "r"(a1), "r"(a2), "r"(a3), "r"(b0), "r"(b1));
}

__device__ __forceinline__ void cpa16(uint32_t saddr, const void* g) {
    asm volatile("cp.async.cg.shared.global [%0], [%1], 16;" :: "r"(saddr), "l"(g));
}
__device__ __forceinline__ void cpa_commit() {
    asm volatile("cp.async.commit_group;");
}
template <int N>
__device__ __forceinline__ void cpa_wait() {
    asm volatile("cp.async.wait_group %0;" :: "n"(N));
}

// ---------------------------------------------------------------------------
// Bias table
// ---------------------------------------------------------------------------
__global__ void bias_table_kernel(const float* __restrict__ rpe) {
    int idx = blockIdx.x * blockDim.x + threadIdx.x;
    if (idx >= NUM_HEADS * S_LEN) return;
    int h = idx / S_LEN;
    int n = idx % S_LEN;
    int bucket;
    if (n < 16) {
        bucket = n;
    } else {
        float t = logf((float)n * 0.0625f);
        float v = t / 5.545177444479562f;
        v = v * 16.0f;
        bucket = 16 + (int)v;
        if (bucket > NUM_BUCKETS - 1) bucket = NUM_BUCKETS - 1;
    }
    g_bias[h * S_LEN + n] = rpe[bucket * NUM_HEADS + h];
}

// ---------------------------------------------------------------------------
// fp32 -> bf16 hi/lo split (elementwise)
// ---------------------------------------------------------------------------
__global__ __launch_bounds__(256) void convert_split_kernel(
    const float* __restrict__ x, __nv_bfloat16* __restrict__ h,
    __nv_bfloat16* __restrict__ l)
{
    int i = (blockIdx.x * 256 + threadIdx.x) * 4;
    float4 v = *(const float4*)(x + i);
    __nv_bfloat162 h01, h23, l01, l23;
    float f[4] = {v.x, v.y, v.z, v.w};
    __nv_bfloat16 hh[4], ll[4];
#pragma unroll
    for (int j = 0; j < 4; j++) {
        hh[j] = __float2bfloat16(f[j]);
        ll[j] = __float2bfloat16(f[j] - __bfloat162float(hh[j]));
    }
    h01.x = hh[0]; h01.y = hh[1]; h23.x = hh[2]; h23.y = hh[3];
    l01.x = ll[0]; l01.y = ll[1]; l23.x = ll[2]; l23.y = ll[3];
    *(__nv_bfloat162*)(h + i)     = h01;
    *(__nv_bfloat162*)(h + i + 2) = h23;
    *(__nv_bfloat162*)(l + i)     = l01;
    *(__nv_bfloat162*)(l + i + 2) = l23;
}

// ---------------------------------------------------------------------------
// W [k][n] fp32 -> transposed Wt [n][k] bf16 hi/lo
// ---------------------------------------------------------------------------
__global__ __launch_bounds__(256) void convert_wT_kernel(
    const float* __restrict__ W, __nv_bfloat16* __restrict__ Th,
    __nv_bfloat16* __restrict__ Tl)
{
    __shared__ float tile[32][33];
    int n0 = blockIdx.x * 32, k0 = blockIdx.y * 32;
    int tx = threadIdx.x & 31, ty = threadIdx.x >> 5;  // 32x8
#pragma unroll
    for (int j = 0; j < 4; j++)
        tile[ty + j * 8][tx] = W[(k0 + ty + j * 8) * D_MODEL + n0 + tx];
    __syncthreads();
#pragma unroll
    for (int j = 0; j < 4; j++) {
        float v = tile[tx][ty + j * 8];
        int n = n0 + ty + j * 8, k = k0 + tx;
        __nv_bfloat16 hi = __float2bfloat16(v);
        __nv_bfloat16 lo = __float2bfloat16(v - __bfloat162float(hi));
        Th[n * D_MODEL + k] = hi;
        Tl[n * D_MODEL + k] = lo;
    }
}

// ---------------------------------------------------------------------------
// bf16x3 tensor-core GEMM: Y[4096,1024] = X @ W + b
// X split hi/lo row-major; W split hi/lo transposed [n][k].
// Block tile 128x128, BK=32, 256 threads = 8 warps (2m x 4n), warp tile 64x32.
// cp.async double-buffered. Smem rows padded to 40 bf16 (conflict-free frags).
// ---------------------------------------------------------------------------
#define GTILE 5120                 // 128*40 bf16 per tile
#define GBUF  (4 * GTILE)          // elements per buffer
#define GSMEM_BYTES (2 * GBUF * 2) // 81920 B

template <bool SCATTER>
__global__ __launch_bounds__(256, 2) void gemm_bf16x3(
    const __nv_bfloat16* __restrict__ Xh, const __nv_bfloat16* __restrict__ Xl,
    const __nv_bfloat16* __restrict__ Wh, const __nv_bfloat16* __restrict__ Wl,
    const float* __restrict__ bias, float* __restrict__ Y)
{
    extern __shared__ __nv_bfloat16 smem[];
    const int tid = threadIdx.x;
    const int lane = tid & 31, warp = tid >> 5;
    const int wm = warp & 1, wn = warp >> 1;
    const int g = lane >> 2, t = lane & 3;
    const int brow = blockIdx.y * 128, bcol = blockIdx.x * 128;

    float acc[4][4][4];
#pragma unroll
    for (int a = 0; a < 4; a++)
#pragma unroll
        for (int b = 0; b < 4; b++)
#pragma unroll
            for (int c = 0; c < 4; c++) acc[a][b][c] = 0.f;

    uint32_t sbase = (uint32_t)__cvta_generic_to_shared(smem);
    const __nv_bfloat16* gsrc[4] = {Xh, Xl, Wh, Wl};
    const int outer0[4] = {brow, brow, bcol, bcol};

    auto load_tiles = [&](int buf, int kk) {
#pragma unroll
        for (int mtx = 0; mtx < 4; mtx++) {
#pragma unroll
            for (int i = 0; i < 2; i++) {
                int chunk = tid + i * 256;
                int row = chunk >> 2, off = chunk & 3;
                uint32_t sa = sbase + (uint32_t)(buf * GBUF + mtx * GTILE) * 2
                              + row * 80 + off * 16;
                const __nv_bfloat16* gp = gsrc[mtx]
                    + (size_t)(outer0[mtx] + row) * D_MODEL + kk + off * 8;
                cpa16(sa, gp);
            }
        }
    };

    load_tiles(0, 0);
    cpa_commit();

    for (int kt = 0; kt < 32; kt++) {
        int buf = kt & 1;
        if (kt + 1 < 32) {
            load_tiles(buf ^ 1, (kt + 1) * 32);
            cpa_commit();
            cpa_wait<1>();
        } else {
            cpa_wait<0>();
        }
        __syncthreads();

        const __nv_bfloat16* sxh = smem + buf * GBUF;
        const __nv_bfloat16* sxl = sxh + GTILE;
        const __nv_bfloat16* swh = sxl + GTILE;
        const __nv_bfloat16* swl = swh + GTILE;

#pragma unroll
        for (int kg = 0; kg < 2; kg++) {
            const int ko = kg * 16 + 2 * t;
            unsigned bh[4][2], bl[4][2];
#pragma unroll
            for (int nt = 0; nt < 4; nt++) {
                int n = wn * 32 + nt * 8 + g;
                bh[nt][0] = *(const unsigned*)&swh[n * 40 + ko];
                bh[nt][1] = *(const unsigned*)&swh[n * 40 + ko + 8];
                bl[nt][0] = *(const unsigned*)&swl[n * 40 + ko];
                bl[nt][1] = *(const unsigned*)&swl[n * 40 + ko + 8];
            }
#pragma unroll
            for (int mt = 0; mt < 4; mt++) {
                int m0 = wm * 64 + mt * 16;
                unsigned ah0 = *(const unsigned*)&sxh[(m0 + g) * 40 + ko];
                unsigned ah1 = *(const unsigned*)&sxh[(m0 + g + 8) * 40 + ko];
                unsigned ah2 = *(const unsigned*)&sxh[(m0 + g) * 40 + ko + 8];
                unsigned ah3 = *(const unsigned*)&sxh[(m0 + g + 8) * 40 + ko + 8];
                unsigned al0 = *(const unsigned*)&sxl[(m0 + g) * 40 + ko];
                unsigned al1 = *(const unsigned*)&sxl[(m0 + g + 8) * 40 + ko];
                unsigned al2 = *(const unsigned*)&sxl[(m0 + g) * 40 + ko + 8];
                unsigned al3 = *(const unsigned*)&sxl[(m0 + g + 8) * 40 + ko + 8];
#pragma unroll
                for (int nt = 0; nt < 4; nt++) {
                    mma_bf16(acc[mt][nt], ah0, ah1, ah2, ah3, bh[nt][0], bh[nt][1]);
                    mma_bf16(acc[mt][nt], ah0, ah1, ah2, ah3, bl[nt][0], bl[nt][1]);
                    mma_bf16(acc[mt][nt], al0, al1, al2, al3, bh[nt][0], bh[nt][1]);
                }
            }
        }
        __syncthreads();
    }

    // epilogue
#pragma unroll
    for (int mt = 0; mt < 4; mt++) {
        int r0 = brow + wm * 64 + mt * 16 + g;
#pragma unroll
        for (int nt = 0; nt < 4; nt++) {
            int col = bcol + wn * 32 + nt * 8 + 2 * t;
            float b0 = bias[col], b1 = bias[col + 1];
            float v00 = acc[mt][nt][0] + b0, v01 = acc[mt][nt][1] + b1;
            float v10 = acc[mt][nt][2] + b0, v11 = acc[mt][nt][3] + b1;
            if (SCATTER) {
                int head = col >> 6, cc = col & 63;
                float* p0 = Y + (size_t)head * S_LEN * DK + (size_t)r0 * DK + cc;
                float* p1 = Y + (size_t)head * S_LEN * DK + (size_t)(r0 + 8) * DK + cc;
                *(float2*)p0 = make_float2(tf32_round(v00), tf32_round(v01));
                *(float2*)p1 = make_float2(tf32_round(v10), tf32_round(v11));
            } else {
                *(float2*)(Y + (size_t)r0 * D_MODEL + col) = make_float2(v00, v01);
                *(float2*)(Y + (size_t)(r0 + 8) * D_MODEL + col) = make_float2(v10, v11);
            }
        }
    }
}

// ---------------------------------------------------------------------------
// Flash attention with mma.sync.m16n8k8.tf32
// ---------------------------------------------------------------------------
#define KS_OFF 0
#define VS_OFF (64 * 68)
#define PS_OFF (VS_OFF + 64 * 72)
#define SB_OFF (PS_OFF + 64 * 68)
#define FM_FLOATS (SB_OFF + 128)

__global__ __launch_bounds__(128) void flash_mma_kernel(float* __restrict__ ctx)
{
    extern __shared__ float sm[];
    float* Ks = sm + KS_OFF;
    float* Vs = sm + VS_OFF;
    float* Ps = sm + PS_OFF;
    float* sbias = sm + SB_OFF;

    const int qt = (int)gridDim.x - 1 - (int)blockIdx.x;
    const int h = blockIdx.y;
    const int qbase = qt * 64;
    const int tid = threadIdx.x;
    const int lane = tid & 31;
    const int w = tid >> 5;
    const int g = lane >> 2;
    const int tig = lane & 3;
    const int wrow = w * 16;
    const int r0 = wrow + g;
    const int r1 = r0 + 8;

    const float* Qg = g_Q + ((size_t)h * S_LEN + qbase + wrow) * DK;
    const float4* Kg4 = (const float4*)(g_K + (size_t)h * S_LEN * DK);
    const float4* Vg4 = (const float4*)(g_V + (size_t)h * S_LEN * DK);

    unsigned qa[8][4];
#pragma unroll
    for (int kc = 0; kc < 8; kc++) {
        qa[kc][0] = __float_as_uint(Qg[g       * DK + kc * 8 + tig]);
        qa[kc][1] = __float_as_uint(Qg[(g + 8) * DK + kc * 8 + tig]);
        qa[kc][2] = __float_as_uint(Qg[g       * DK + kc * 8 + tig + 4]);
        qa[kc][3] = __float_as_uint(Qg[(g + 8) * DK + kc * 8 + tig + 4]);
    }

    float O[8][4];
#pragma unroll
    for (int db = 0; db < 8; db++)
#pragma unroll
        for (int c = 0; c < 4; c++) O[db][c] = 0.f;

    float m0 = -INFINITY, m1 = -INFINITY, l0 = 0.f, l1 = 0.f;

    for (int kt = 0; kt <= qt; kt++) {
        const int kbase = kt * 64;
        const int d0 = qbase - kbase;

        __syncthreads();
#pragma unroll
        for (int i = 0; i < 8; i++) {
            int idx = tid + i * 128;
            int key = idx >> 4, d4 = idx & 15;
            float4 kv = Kg4[kbase * 16 + idx];
            float4 vv = Vg4[kbase * 16 + idx];
            *(float4*)&Ks[key * 68 + d4 * 4] = kv;
            *(float4*)&Vs[key * 72 + d4 * 4] = vv;
        }
        if (tid < 127) {
            int delta = d0 - 63 + tid;
            sbias[tid] = (delta >= 0) ? g_bias[h * S_LEN + delta] : 0.f;
        }
        __syncthreads();

        if (kbase > qbase + wrow + 15) continue;

        float Sc[8][4];
#pragma unroll
        for (int nb = 0; nb < 8; nb++)
#pragma unroll
            for (int c = 0; c < 4; c++) Sc[nb][c] = 0.f;

#pragma unroll
        for (int kc = 0; kc < 8; kc++) {
#pragma unroll
            for (int nb = 0; nb < 8; nb++) {
                unsigned b0 = __float_as_uint(Ks[(nb * 8 + g) * 68 + kc * 8 + tig]);
                unsigned b1 = __float_as_uint(Ks[(nb * 8 + g) * 68 + kc * 8 + tig + 4]);
                mma_tf32(Sc[nb], qa[kc][0], qa[kc][1], qa[kc][2], qa[kc][3], b0, b1);
            }
        }

        float mt0 = -INFINITY, mt1 = -INFINITY;
#pragma unroll
        for (int nb = 0; nb < 8; nb++) {
            int col0 = nb * 8 + 2 * tig;
            float v00 = Sc[nb][0] * 0.125f + sbias[r0 - col0 + 63];
            float v01 = Sc[nb][1] * 0.125f + sbias[r0 - col0 + 62];
            float v10 = Sc[nb][2] * 0.125f + sbias[r1 - col0 + 63];
            float v11 = Sc[nb][3] * 0.125f + sbias[r1 - col0 + 62];
            Sc[nb][0] = (d0 + r0 - col0     >= 0) ? v00 : -1e30f;
            Sc[nb][1] = (d0 + r0 - col0 - 1 >= 0) ? v01 : -1e30f;
            Sc[nb][2] = (d0 + r1 - col0     >= 0) ? v10 : -1e30f;
            Sc[nb][3] = (d0 + r1 - col0 - 1 >= 0) ? v11 : -1e30f;
            mt0 = fmaxf(mt0, fmaxf(Sc[nb][0], Sc[nb][1]));
            mt1 = fmaxf(mt1, fmaxf(Sc[nb][2], Sc[nb][3]));
        }
        mt0 = fmaxf(mt0, __shfl_xor_sync(0xffffffffu, mt0, 1));
        mt0 = fmaxf(mt0, __shfl_xor_sync(0xffffffffu, mt0, 2));
        mt1 = fmaxf(mt1, __shfl_xor_sync(0xffffffffu, mt1, 1));
        mt1 = fmaxf(mt1, __shfl_xor_sync(0xffffffffu, mt1, 2));

        float mn0 = fmaxf(m0, mt0), mn1 = fmaxf(m1, mt1);
        float corr0 = __expf(m0 - mn0), corr1 = __expf(m1 - mn1);
        float ls0 = 0.f, ls1 = 0.f;
#pragma unroll
        for (int nb = 0; nb < 8; nb++) {
            Sc[nb][0] = __expf(Sc[nb][0] - mn0);
            Sc[nb][1] = __expf(Sc[nb][1] - mn0);
            Sc[nb][2] = __expf(Sc[nb][2] - mn1);
            Sc[nb][3] = __expf(Sc[nb][3] - mn1);
            ls0 += Sc[nb][0] + Sc[nb][1];
            ls1 += Sc[nb][2] + Sc[nb][3];
        }
        ls0 += __shfl_xor_sync(0xffffffffu, ls0, 1);
        ls0 += __shfl_xor_sync(0xffffffffu, ls0, 2);
        ls1 += __shfl_xor_sync(0xffffffffu, ls1, 1);
        ls1 += __shfl_xor_sync(0xffffffffu, ls1, 2);
        l0 = l0 * corr0 + ls0;  m0 = mn0;
        l1 = l1 * corr1 + ls1;  m1 = mn1;

#pragma unroll
        for (int db = 0; db < 8; db++) {
            O[db][0] *= corr0; O[db][1] *= corr0;
            O[db][2] *= corr1; O[db][3] *= corr1;
        }

#pragma unroll
        for (int nb = 0; nb < 8; nb++) {
            int col0 = nb * 8 + 2 * tig;
            float2 p0 = make_float2(tf32_round(Sc[nb][0]), tf32_round(Sc[nb][1]));
            float2 p1 = make_float2(tf32_round(Sc[nb][2]), tf32_round(Sc[nb][3]));
            *(float2*)&Ps[r0 * 68 + col0] = p0;
            *(float2*)&Ps[r1 * 68 + col0] = p1;
        }
        __syncwarp();

#pragma unroll
        for (int kc2 = 0; kc2 < 8; kc2++) {
            unsigned pa0 = __float_as_uint(Ps[r0 * 68 + kc2 * 8 + tig]);
            unsigned pa1 = __float_as_uint(Ps[r1 * 68 + kc2 * 8 + tig]);
            unsigned pa2 = __float_as_uint(Ps[r0 * 68 + kc2 * 8 + tig + 4]);
            unsigned pa3 = __float_as_uint(Ps[r1 * 68 + kc2 * 8 + tig + 4]);
#pragma unroll
            for (int db = 0; db < 8; db++) {
                unsigned vb0 = __float_as_uint(Vs[(kc2 * 8 + tig)     * 72 + db * 8 + g]);
                unsigned vb1 = __float_as_uint(Vs[(kc2 * 8 + tig + 4) * 72 + db * 8 + g]);
                mma_tf32(O[db], pa0, pa1, pa2, pa3, vb0, vb1);
            }
        }
    }

    float inv0 = 1.f / l0, inv1 = 1.f / l1;
    float* dst0 = ctx + (size_t)(qbase + r0) * D_MODEL + h * DK;
    float* dst1 = ctx + (size_t)(qbase + r1) * D_MODEL + h * DK;
#pragma unroll
    for (int db = 0; db < 8; db++) {
        int col0 = db * 8 + 2 * tig;
        *(float2*)&dst0[col0] = make_float2(O[db][0] * inv0, O[db][1] * inv0);
        *(float2*)&dst1[col0] = make_float2(O[db][2] * inv1, O[db][3] * inv1);
    }
}

// ---------------------------------------------------------------------------
extern "C" void kernel_launch(void* const* d_in, const int* in_sizes, int n_in,
                              void* d_out, int out_size)
{
    const float* query = (const float*)d_in[0];
    const float* key   = (const float*)d_in[1];
    const float* value = (const float*)d_in[2];
    const float* Wq = (const float*)d_in[4];
    const float* bq = (const float*)d_in[5];
    const float* Wk = (const float*)d_in[6];
    const float* bk = (const float*)d_in[7];
    const float* Wv = (const float*)d_in[8];
    const float* bv = (const float*)d_in[9];
    const float* Wo = (const float*)d_in[10];
    const float* bo = (const float*)d_in[11];
    const float* rpe = (const float*)d_in[12];
    float* out = (float*)d_out;

    float *gQ, *gK, *gV, *gctx;
    cudaGetSymbolAddress((void**)&gQ, g_Q);
    cudaGetSymbolAddress((void**)&gK, g_K);
    cudaGetSymbolAddress((void**)&gV, g_V);
    cudaGetSymbolAddress((void**)&gctx, g_ctx);
    __nv_bfloat16 *xh, *xl, *ch, *cl, *wth, *wtl;
    cudaGetSymbolAddress((void**)&xh, g_XH);
    cudaGetSymbolAddress((void**)&xl, g_XL);
    cudaGetSymbolAddress((void**)&ch, g_CH);
    cudaGetSymbolAddress((void**)&cl, g_CL);
    cudaGetSymbolAddress((void**)&wth, g_WTH);
    cudaGetSymbolAddress((void**)&wtl, g_WTL);

    const int XN = S_LEN * D_MODEL;
    const int WN = D_MODEL * D_MODEL;

    // bias table
    bias_table_kernel<<<(NUM_HEADS * S_LEN + 255) / 256, 256>>>(rpe);

    // splits
    int cgrid = XN / 4 / 256;
    convert_split_kernel<<<cgrid, 256>>>(query, xh,            xl);
    convert_split_kernel<<<cgrid, 256>>>(key,   xh + XN,       xl + XN);
    convert_split_kernel<<<cgrid, 256>>>(value, xh + 2 * XN,   xl + 2 * XN);
    dim3 wgrid(D_MODEL / 32, D_MODEL / 32);
    convert_wT_kernel<<<wgrid, 256>>>(Wq, wth,          wtl);
    convert_wT_kernel<<<wgrid, 256>>>(Wk, wth + WN,     wtl + WN);
    convert_wT_kernel<<<wgrid, 256>>>(Wv, wth + 2 * WN, wtl + 2 * WN);
    convert_wT_kernel<<<wgrid, 256>>>(Wo, wth + 3 * WN, wtl + 3 * WN);

    // projections (tensor core, bf16x3) -> [H][S][DK] tf32-rounded
    cudaFuncSetAttribute(gemm_bf16x3<true>,
                         cudaFuncAttributeMaxDynamicSharedMemorySize, GSMEM_BYTES);
    cudaFuncSetAttribute(gemm_bf16x3<false>,
                         cudaFuncAttributeMaxDynamicSharedMemorySize, GSMEM_BYTES);
    dim3 ggrid(D_MODEL / 128, S_LEN / 128);
    gemm_bf16x3<true><<<ggrid, 256, GSMEM_BYTES>>>(xh,          xl,          wth,          wtl,          bq, gQ);
    gemm_bf16x3<true><<<ggrid, 256, GSMEM_BYTES>>>(xh + XN,     xl + XN,     wth + WN,     wtl + WN,     bk, gK);
    gemm_bf16x3<true><<<ggrid, 256, GSMEM_BYTES>>>(xh + 2 * XN, xl + 2 * XN, wth + 2 * WN, wtl + 2 * WN, bv, gV);

    // flash attention (tensor-core tf32)
    size_t smem_bytes = FM_FLOATS * sizeof(float);
    cudaFuncSetAttribute(flash_mma_kernel, cudaFuncAttributeMaxDynamicSharedMemorySize,
                         (int)smem_bytes);
    dim3 fgrid(S_LEN / 64, NUM_HEADS);
    flash_mma_kernel<<<fgrid, 128, smem_bytes>>>(gctx);

    // output projection
    convert_split_kernel<<<cgrid, 256>>>(gctx, ch, cl);
    gemm_bf16x3<false><<<ggrid, 256, GSMEM_BYTES>>>(ch, cl, wth + 3 * WN, wtl + 3 * WN, bo, out);
    (void)in_sizes; (void)n_in; (void)out_size;
}

// round 5
// speedup vs baseline: 13.9206x; 1.0621x over previous
#include <cuda_runtime.h>
#include <cuda_bf16.h>
#include <math.h>
#include <stdint.h>
#include <cstdint>

// Problem constants
#define S_LEN 4096
#define D_MODEL 1024
#define NUM_HEADS 16
#define DK 64
#define NUM_BUCKETS 32

// Scratch (device globals: no allocation allowed)
__device__ float g_Q[NUM_HEADS * S_LEN * DK];
__device__ float g_K[NUM_HEADS * S_LEN * DK];
__device__ float g_V[NUM_HEADS * S_LEN * DK];
__device__ float g_bias[NUM_HEADS * S_LEN];

// bf16 split operands
__device__ __nv_bfloat16 g_XH[3 * S_LEN * D_MODEL];
__device__ __nv_bfloat16 g_XL[3 * S_LEN * D_MODEL];
__device__ __nv_bfloat16 g_CH[S_LEN * D_MODEL];
__device__ __nv_bfloat16 g_CL[S_LEN * D_MODEL];
__device__ __nv_bfloat16 g_WTH[4 * D_MODEL * D_MODEL];   // transposed [n][k]
__device__ __nv_bfloat16 g_WTL[4 * D_MODEL * D_MODEL];

// ---------------------------------------------------------------------------
// helpers
// ---------------------------------------------------------------------------
__device__ __forceinline__ float tf32_round(float x) {
    unsigned u;
    asm("cvt.rna.tf32.f32 %0, %1;" : "=r"(u) : "f"(x));
    return __uint_as_float(u);
}

__device__ __forceinline__ void mma_tf32(float c[4],
                                         unsigned a0, unsigned a1, unsigned a2, unsigned a3,
                                         unsigned b0, unsigned b1) {
    asm volatile(
        "mma.sync.aligned.m16n8k8.row.col.f32.tf32.tf32.f32 "
        "{%0,%1,%2,%3}, {%4,%5,%6,%7}, {%8,%9}, {%0,%1,%2,%3};"
        : "+f"(c[0]), "+f"(c[1]), "+f"(c[2]), "+f"(c[3])
        : "r"(a0), "r"(a1), "r"(a2), "r"(a3), "r"(b0), "r"(b1));
}

__device__ __forceinline__ void mma_bf16(float c[4],
                                         unsigned a0, unsigned a1, unsigned a2, unsigned a3,
                                         unsigned b0, unsigned b1) {
    asm volatile(
        "mma.sync.aligned.m16n8k16.row.col.f32.bf16.bf16.f32 "
        "{%0,%1,%2,%3}, {%4,%5,%6,%7}, {%8,%9}, {%0,%1,%2,%3};"
        : "+f"(c[0]), "+f"(c[1]), "+f"(c[2]), "+f"(c[3])
        : "r"(a0), "r"(a1), "r"(a2), "r"(a3), "r"(b0), "r"(b1));
}

__device__ __forceinline__ void ldsm4(unsigned &r0, unsigned &r1, unsigned &r2,
                                      unsigned &r3, uint32_t addr) {
    asm volatile("ldmatrix.sync.aligned.m8n8.x4.shared.b16 {%0,%1,%2,%3}, [%4];"
                 : "=r"(r0), "=r"(r1), "=r"(r2), "=r"(r3) : "r"(addr));
}

__device__ __forceinline__ void cpa16(uint32_t saddr, const void* g) {
    asm volatile("cp.async.cg.shared.global [%0], [%1], 16;" :: "r"(saddr), "l"(g));
}
__device__ __forceinline__ void cpa4(uint32_t saddr, const void* g) {
    asm volatile("cp.async.ca.shared.global [%0], [%1], 4;" :: "r"(saddr), "l"(g));
}
__device__ __forceinline__ void cpa_commit() {
    asm volatile("cp.async.commit_group;");
}
template <int N>
__device__ __forceinline__ void cpa_wait() {
    asm volatile("cp.async.wait_group %0;" :: "n"(N));
}

// ---------------------------------------------------------------------------
// Bias table
// ---------------------------------------------------------------------------
__global__ void bias_table_kernel(const float* __restrict__ rpe) {
    int idx = blockIdx.x * blockDim.x + threadIdx.x;
    if (idx >= NUM_HEADS * S_LEN) return;
    int h = idx / S_LEN;
    int n = idx % S_LEN;
    int bucket;
    if (n < 16) {
        bucket = n;
    } else {
        float t = logf((float)n * 0.0625f);
        float v = t / 5.545177444479562f;
        v = v * 16.0f;
        bucket = 16 + (int)v;
        if (bucket > NUM_BUCKETS - 1) bucket = NUM_BUCKETS - 1;
    }
    g_bias[h * S_LEN + n] = rpe[bucket * NUM_HEADS + h];
}

// ---------------------------------------------------------------------------
// fp32 -> bf16 hi/lo split (elementwise)
// ---------------------------------------------------------------------------
__global__ __launch_bounds__(256) void convert_split_kernel(
    const float* __restrict__ x, __nv_bfloat16* __restrict__ h,
    __nv_bfloat16* __restrict__ l)
{
    int i = (blockIdx.x * 256 + threadIdx.x) * 4;
    float4 v = *(const float4*)(x + i);
    float f[4] = {v.x, v.y, v.z, v.w};
    __nv_bfloat16 hh[4], ll[4];
#pragma unroll
    for (int j = 0; j < 4; j++) {
        hh[j] = __float2bfloat16(f[j]);
        ll[j] = __float2bfloat16(f[j] - __bfloat162float(hh[j]));
    }
    __nv_bfloat162 h01, h23, l01, l23;
    h01.x = hh[0]; h01.y = hh[1]; h23.x = hh[2]; h23.y = hh[3];
    l01.x = ll[0]; l01.y = ll[1]; l23.x = ll[2]; l23.y = ll[3];
    *(__nv_bfloat162*)(h + i)     = h01;
    *(__nv_bfloat162*)(h + i + 2) = h23;
    *(__nv_bfloat162*)(l + i)     = l01;
    *(__nv_bfloat162*)(l + i + 2) = l23;
}

// ---------------------------------------------------------------------------
// W [k][n] fp32 -> transposed Wt [n][k] bf16 hi/lo
// ---------------------------------------------------------------------------
__global__ __launch_bounds__(256) void convert_wT_kernel(
    const float* __restrict__ W, __nv_bfloat16* __restrict__ Th,
    __nv_bfloat16* __restrict__ Tl)
{
    __shared__ float tile[32][33];
    int n0 = blockIdx.x * 32, k0 = blockIdx.y * 32;
    int tx = threadIdx.x & 31, ty = threadIdx.x >> 5;  // 32x8
#pragma unroll
    for (int j = 0; j < 4; j++)
        tile[ty + j * 8][tx] = W[(k0 + ty + j * 8) * D_MODEL + n0 + tx];
    __syncthreads();
#pragma unroll
    for (int j = 0; j < 4; j++) {
        float v = tile[tx][ty + j * 8];
        int n = n0 + ty + j * 8, k = k0 + tx;
        __nv_bfloat16 hi = __float2bfloat16(v);
        __nv_bfloat16 lo = __float2bfloat16(v - __bfloat162float(hi));
        Th[n * D_MODEL + k] = hi;
        Tl[n * D_MODEL + k] = lo;
    }
}

// ---------------------------------------------------------------------------
// bf16x3 tensor-core GEMM with ldmatrix fragment loads.
// Block tile 128x128, BK=32, 256 threads = 8 warps (2m x 4n), warp tile 64x32.
// ---------------------------------------------------------------------------
#define GTILE 5120                 // 128*40 bf16 per tile
#define GBUF  (4 * GTILE)          // elements per buffer
#define GSMEM_BYTES (2 * GBUF * 2) // 81920 B

template <bool SCATTER>
__global__ __launch_bounds__(256, 2) void gemm_bf16x3(
    const __nv_bfloat16* __restrict__ Xh, const __nv_bfloat16* __restrict__ Xl,
    const __nv_bfloat16* __restrict__ Wh, const __nv_bfloat16* __restrict__ Wl,
    const float* __restrict__ bias, float* __restrict__ Y)
{
    extern __shared__ __nv_bfloat16 smem[];
    const int tid = threadIdx.x;
    const int lane = tid & 31, warp = tid >> 5;
    const int wm = warp & 1, wn = warp >> 1;
    const int g = lane >> 2, t = lane & 3;
    const int brow = blockIdx.y * 128, bcol = blockIdx.x * 128;

    float acc[4][4][4];
#pragma unroll
    for (int a = 0; a < 4; a++)
#pragma unroll
        for (int b = 0; b < 4; b++)
#pragma unroll
            for (int c = 0; c < 4; c++) acc[a][b][c] = 0.f;

    uint32_t sbase = (uint32_t)__cvta_generic_to_shared(smem);
    const __nv_bfloat16* gsrc[4] = {Xh, Xl, Wh, Wl};
    const int outer0[4] = {brow, brow, bcol, bcol};

    // ldmatrix per-lane byte offsets
    const uint32_t laneA = (uint32_t)(((lane & 15) * 40 + (lane >> 4) * 8) * 2);
    const uint32_t laneB = (uint32_t)((((lane & 7) + ((lane >> 4) << 3)) * 40
                                      + (((lane >> 3) & 1) * 8)) * 2);

    auto load_tiles = [&](int buf, int kk) {
#pragma unroll
        for (int mtx = 0; mtx < 4; mtx++) {
#pragma unroll
            for (int i = 0; i < 2; i++) {
                int chunk = tid + i * 256;
                int row = chunk >> 2, off = chunk & 3;
                uint32_t sa = sbase + (uint32_t)(buf * GBUF + mtx * GTILE) * 2
                              + row * 80 + off * 16;
                const __nv_bfloat16* gp = gsrc[mtx]
                    + (size_t)(outer0[mtx] + row) * D_MODEL + kk + off * 8;
                cpa16(sa, gp);
            }
        }
    };

    load_tiles(0, 0);
    cpa_commit();

    for (int kt = 0; kt < 32; kt++) {
        int buf = kt & 1;
        if (kt + 1 < 32) {
            load_tiles(buf ^ 1, (kt + 1) * 32);
            cpa_commit();
            cpa_wait<1>();
        } else {
            cpa_wait<0>();
        }
        __syncthreads();

        const uint32_t bxh = sbase + (uint32_t)(buf * GBUF) * 2;
        const uint32_t bxl = bxh + GTILE * 2;
        const uint32_t bwh = bxl + GTILE * 2;
        const uint32_t bwl = bwh + GTILE * 2;

#pragma unroll
        for (int kg = 0; kg < 2; kg++) {
            const uint32_t kofs = (uint32_t)(kg * 16 * 2);
            unsigned bh[4][2], bl[4][2];
            ldsm4(bh[0][0], bh[0][1], bh[1][0], bh[1][1],
                  bwh + laneB + (uint32_t)((wn * 32) * 40 * 2) + kofs);
            ldsm4(bh[2][0], bh[2][1], bh[3][0], bh[3][1],
                  bwh + laneB + (uint32_t)((wn * 32 + 16) * 40 * 2) + kofs);
            ldsm4(bl[0][0], bl[0][1], bl[1][0], bl[1][1],
                  bwl + laneB + (uint32_t)((wn * 32) * 40 * 2) + kofs);
            ldsm4(bl[2][0], bl[2][1], bl[3][0], bl[3][1],
                  bwl + laneB + (uint32_t)((wn * 32 + 16) * 40 * 2) + kofs);
#pragma unroll
            for (int mt = 0; mt < 4; mt++) {
                const uint32_t rofs = (uint32_t)((wm * 64 + mt * 16) * 40 * 2);
                unsigned ah[4], al[4];
                ldsm4(ah[0], ah[1], ah[2], ah[3], bxh + laneA + rofs + kofs);
                ldsm4(al[0], al[1], al[2], al[3], bxl + laneA + rofs + kofs);
#pragma unroll
                for (int nt = 0; nt < 4; nt++) {
                    mma_bf16(acc[mt][nt], ah[0], ah[1], ah[2], ah[3], bh[nt][0], bh[nt][1]);
                    mma_bf16(acc[mt][nt], ah[0], ah[1], ah[2], ah[3], bl[nt][0], bl[nt][1]);
                    mma_bf16(acc[mt][nt], al[0], al[1], al[2], al[3], bh[nt][0], bh[nt][1]);
                }
            }
        }
        __syncthreads();
    }

    // epilogue
#pragma unroll
    for (int mt = 0; mt < 4; mt++) {
        int r0 = brow + wm * 64 + mt * 16 + g;
#pragma unroll
        for (int nt = 0; nt < 4; nt++) {
            int col = bcol + wn * 32 + nt * 8 + 2 * t;
            float b0 = bias[col], b1 = bias[col + 1];
            float v00 = acc[mt][nt][0] + b0, v01 = acc[mt][nt][1] + b1;
            float v10 = acc[mt][nt][2] + b0, v11 = acc[mt][nt][3] + b1;
            if (SCATTER) {
                int head = col >> 6, cc = col & 63;
                float* p0 = Y + (size_t)head * S_LEN * DK + (size_t)r0 * DK + cc;
                float* p1 = Y + (size_t)head * S_LEN * DK + (size_t)(r0 + 8) * DK + cc;
                *(float2*)p0 = make_float2(tf32_round(v00), tf32_round(v01));
                *(float2*)p1 = make_float2(tf32_round(v10), tf32_round(v11));
            } else {
                *(float2*)(Y + (size_t)r0 * D_MODEL + col) = make_float2(v00, v01);
                *(float2*)(Y + (size_t)(r0 + 8) * D_MODEL + col) = make_float2(v10, v11);
            }
        }
    }
}

// ---------------------------------------------------------------------------
// Flash attention v2: q-tile 128 (8 warps x 16 rows), k-tile 64,
// cp.async double-buffered K/V/bias, tf32 MMA. Epilogue writes bf16 hi/lo
// context directly (fused split for the output projection).
// ---------------------------------------------------------------------------
#define F_KS 0
#define F_KBUF 4352                  // 64*68
#define F_VS (2 * F_KBUF)            // 8704
#define F_VBUF 4608                  // 64*72
#define F_PS (F_VS + 2 * F_VBUF)     // 17920
#define F_SB (F_PS + 128 * 68)       // 26624
#define F_SBUF 192
#define F_FLOATS (F_SB + 2 * F_SBUF) // 27008 floats = 108032 B

__global__ __launch_bounds__(256) void flash_mma_kernel(
    __nv_bfloat16* __restrict__ ctxh, __nv_bfloat16* __restrict__ ctxl)
{
    extern __shared__ float sm[];
    const int qt = 31 - (int)blockIdx.x;   // biggest tiles first
    const int h = blockIdx.y;
    const int qbase = qt * 128;
    const int tid = threadIdx.x;
    const int lane = tid & 31, w = tid >> 5;
    const int g = lane >> 2, t = lane & 3;
    const int wrow = w * 16;
    const int r0 = wrow + g, r1 = r0 + 8;

    const float* Qg = g_Q + ((size_t)h * S_LEN + qbase + wrow) * DK;
    const float* Kg = g_K + (size_t)h * S_LEN * DK;
    const float* Vg = g_V + (size_t)h * S_LEN * DK;
    const float* Bg = g_bias + h * S_LEN;

    uint32_t sb32 = (uint32_t)__cvta_generic_to_shared(sm);

    auto load_tile = [&](int b, int kt2) {
        const int kb = kt2 * 64;
        const float4* K4 = (const float4*)(Kg + (size_t)kb * DK);
        const float4* V4 = (const float4*)(Vg + (size_t)kb * DK);
#pragma unroll
        for (int i = 0; i < 4; i++) {
            int idx = tid + i * 256;
            int key = idx >> 4, d4 = idx & 15;
            cpa16(sb32 + (uint32_t)(F_KS + b * F_KBUF + key * 68 + d4 * 4) * 4, K4 + idx);
            cpa16(sb32 + (uint32_t)(F_VS + b * F_VBUF + key * 72 + d4 * 4) * 4, V4 + idx);
        }
        int dd0 = qbase - kb;
        if (tid < 191) {
            if (dd0 >= 63) {
                cpa4(sb32 + (uint32_t)(F_SB + b * F_SBUF + tid) * 4, Bg + dd0 - 63 + tid);
            } else {
                int delta = dd0 - 63 + tid;
                sm[F_SB + b * F_SBUF + tid] = (delta >= 0) ? Bg[delta] : 0.f;
            }
        }
    };

    // Q fragments (tf32 bits)
    unsigned qa[8][4];
#pragma unroll
    for (int kc = 0; kc < 8; kc++) {
        qa[kc][0] = __float_as_uint(Qg[g       * DK + kc * 8 + t]);
        qa[kc][1] = __float_as_uint(Qg[(g + 8) * DK + kc * 8 + t]);
        qa[kc][2] = __float_as_uint(Qg[g       * DK + kc * 8 + t + 4]);
        qa[kc][3] = __float_as_uint(Qg[(g + 8) * DK + kc * 8 + t + 4]);
    }

    float O[8][4];
#pragma unroll
    for (int db = 0; db < 8; db++)
#pragma unroll
        for (int c = 0; c < 4; c++) O[db][c] = 0.f;
    float m0 = -INFINITY, m1 = -INFINITY, l0 = 0.f, l1 = 0.f;

    const int ktmax = 2 * qt + 1;
    load_tile(0, 0);
    cpa_commit();

    for (int kt = 0; kt <= ktmax; kt++) {
        const int buf = kt & 1;
        if (kt < ktmax) {
            load_tile(buf ^ 1, kt + 1);
            cpa_commit();
            cpa_wait<1>();
        } else {
            cpa_wait<0>();
        }
        __syncthreads();

        const int kbase = kt * 64;
        const int d0 = qbase - kbase;

        if (kbase <= qbase + wrow + 15) {
            const float* Ks = sm + F_KS + buf * F_KBUF;
            const float* Vs = sm + F_VS + buf * F_VBUF;
            const float* Sb = sm + F_SB + buf * F_SBUF;
            float* Pw = sm + F_PS + wrow * 68;

            // ---- S = Q @ K^T ----
            float Sc[8][4];
#pragma unroll
            for (int nb = 0; nb < 8; nb++)
#pragma unroll
                for (int c = 0; c < 4; c++) Sc[nb][c] = 0.f;
#pragma unroll
            for (int kc = 0; kc < 8; kc++) {
#pragma unroll
                for (int nb = 0; nb < 8; nb++) {
                    unsigned b0 = __float_as_uint(Ks[(nb * 8 + g) * 68 + kc * 8 + t]);
                    unsigned b1 = __float_as_uint(Ks[(nb * 8 + g) * 68 + kc * 8 + t + 4]);
                    mma_tf32(Sc[nb], qa[kc][0], qa[kc][1], qa[kc][2], qa[kc][3], b0, b1);
                }
            }

            // ---- scale + bias + causal mask + running max ----
            float mt0 = -INFINITY, mt1 = -INFINITY;
#pragma unroll
            for (int nb = 0; nb < 8; nb++) {
                int col0 = nb * 8 + 2 * t;
                float v00 = Sc[nb][0] * 0.125f + Sb[r0 - col0 + 63];
                float v01 = Sc[nb][1] * 0.125f + Sb[r0 - col0 + 62];
                float v10 = Sc[nb][2] * 0.125f + Sb[r1 - col0 + 63];
                float v11 = Sc[nb][3] * 0.125f + Sb[r1 - col0 + 62];
                Sc[nb][0] = (d0 + r0 - col0     >= 0) ? v00 : -1e30f;
                Sc[nb][1] = (d0 + r0 - col0 - 1 >= 0) ? v01 : -1e30f;
                Sc[nb][2] = (d0 + r1 - col0     >= 0) ? v10 : -1e30f;
                Sc[nb][3] = (d0 + r1 - col0 - 1 >= 0) ? v11 : -1e30f;
                mt0 = fmaxf(mt0, fmaxf(Sc[nb][0], Sc[nb][1]));
                mt1 = fmaxf(mt1, fmaxf(Sc[nb][2], Sc[nb][3]));
            }
            mt0 = fmaxf(mt0, __shfl_xor_sync(0xffffffffu, mt0, 1));
            mt0 = fmaxf(mt0, __shfl_xor_sync(0xffffffffu, mt0, 2));
            mt1 = fmaxf(mt1, __shfl_xor_sync(0xffffffffu, mt1, 1));
            mt1 = fmaxf(mt1, __shfl_xor_sync(0xffffffffu, mt1, 2));

            float mn0 = fmaxf(m0, mt0), mn1 = fmaxf(m1, mt1);
            float corr0 = __expf(m0 - mn0), corr1 = __expf(m1 - mn1);
            float ls0 = 0.f, ls1 = 0.f;
#pragma unroll
            for (int nb = 0; nb < 8; nb++) {
                Sc[nb][0] = __expf(Sc[nb][0] - mn0);
                Sc[nb][1] = __expf(Sc[nb][1] - mn0);
                Sc[nb][2] = __expf(Sc[nb][2] - mn1);
                Sc[nb][3] = __expf(Sc[nb][3] - mn1);
                ls0 += Sc[nb][0] + Sc[nb][1];
                ls1 += Sc[nb][2] + Sc[nb][3];
            }
            ls0 += __shfl_xor_sync(0xffffffffu, ls0, 1);
            ls0 += __shfl_xor_sync(0xffffffffu, ls0, 2);
            ls1 += __shfl_xor_sync(0xffffffffu, ls1, 1);
            ls1 += __shfl_xor_sync(0xffffffffu, ls1, 2);
            l0 = l0 * corr0 + ls0;  m0 = mn0;
            l1 = l1 * corr1 + ls1;  m1 = mn1;

#pragma unroll
            for (int db = 0; db < 8; db++) {
                O[db][0] *= corr0; O[db][1] *= corr0;
                O[db][2] *= corr1; O[db][3] *= corr1;
            }

            // ---- stage P (tf32-rounded) into warp-private smem ----
#pragma unroll
            for (int nb = 0; nb < 8; nb++) {
                int col0 = nb * 8 + 2 * t;
                *(float2*)&Pw[g * 68 + col0] =
                    make_float2(tf32_round(Sc[nb][0]), tf32_round(Sc[nb][1]));
                *(float2*)&Pw[(g + 8) * 68 + col0] =
                    make_float2(tf32_round(Sc[nb][2]), tf32_round(Sc[nb][3]));
            }
            __syncwarp();

            // ---- O += P @ V ----
#pragma unroll
            for (int kc2 = 0; kc2 < 8; kc2++) {
                unsigned pa0 = __float_as_uint(Pw[g       * 68 + kc2 * 8 + t]);
                unsigned pa1 = __float_as_uint(Pw[(g + 8) * 68 + kc2 * 8 + t]);
                unsigned pa2 = __float_as_uint(Pw[g       * 68 + kc2 * 8 + t + 4]);
                unsigned pa3 = __float_as_uint(Pw[(g + 8) * 68 + kc2 * 8 + t + 4]);
#pragma unroll
                for (int db = 0; db < 8; db++) {
                    unsigned vb0 = __float_as_uint(Vs[(kc2 * 8 + t)     * 72 + db * 8 + g]);
                    unsigned vb1 = __float_as_uint(Vs[(kc2 * 8 + t + 4) * 72 + db * 8 + g]);
                    mma_tf32(O[db], pa0, pa1, pa2, pa3, vb0, vb1);
                }
            }
        }
        __syncthreads();
    }

    // ---- normalize + fused bf16 hi/lo split write ----
    float inv0 = 1.f / l0, inv1 = 1.f / l1;
    const size_t grow0 = (size_t)(qbase + r0) * D_MODEL;
    const size_t grow1 = (size_t)(qbase + r1) * D_MODEL;
#pragma unroll
    for (int db = 0; db < 8; db++) {
        int col = h * DK + db * 8 + 2 * t;
        float v00 = O[db][0] * inv0, v01 = O[db][1] * inv0;
        float v10 = O[db][2] * inv1, v11 = O[db][3] * inv1;
        __nv_bfloat162 h0, l0v, h1, l1v;
        h0.x = __float2bfloat16(v00); h0.y = __float2bfloat16(v01);
        l0v.x = __float2bfloat16(v00 - __bfloat162float(h0.x));
        l0v.y = __float2bfloat16(v01 - __bfloat162float(h0.y));
        h1.x = __float2bfloat16(v10); h1.y = __float2bfloat16(v11);
        l1v.x = __float2bfloat16(v10 - __bfloat162float(h1.x));
        l1v.y = __float2bfloat16(v11 - __bfloat162float(h1.y));
        *(__nv_bfloat162*)(ctxh + grow0 + col) = h0;
        *(__nv_bfloat162*)(ctxl + grow0 + col) = l0v;
        *(__nv_bfloat162*)(ctxh + grow1 + col) = h1;
        *(__nv_bfloat162*)(ctxl + grow1 + col) = l1v;
    }
}

// ---------------------------------------------------------------------------
extern "C" void kernel_launch(void* const* d_in, const int* in_sizes, int n_in,
                              void* d_out, int out_size)
{
    const float* query = (const float*)d_in[0];
    const float* key   = (const float*)d_in[1];
    const float* value = (const float*)d_in[2];
    const float* Wq = (const float*)d_in[4];
    const float* bq = (const float*)d_in[5];
    const float* Wk = (const float*)d_in[6];
    const float* bk = (const float*)d_in[7];
    const float* Wv = (const float*)d_in[8];
    const float* bv = (const float*)d_in[9];
    const float* Wo = (const float*)d_in[10];
    const float* bo = (const float*)d_in[11];
    const float* rpe = (const float*)d_in[12];
    float* out = (float*)d_out;

    float *gQ, *gK, *gV;
    cudaGetSymbolAddress((void**)&gQ, g_Q);
    cudaGetSymbolAddress((void**)&gK, g_K);
    cudaGetSymbolAddress((void**)&gV, g_V);
    __nv_bfloat16 *xh, *xl, *ch, *cl, *wth, *wtl;
    cudaGetSymbolAddress((void**)&xh, g_XH);
    cudaGetSymbolAddress((void**)&xl, g_XL);
    cudaGetSymbolAddress((void**)&ch, g_CH);
    cudaGetSymbolAddress((void**)&cl, g_CL);
    cudaGetSymbolAddress((void**)&wth, g_WTH);
    cudaGetSymbolAddress((void**)&wtl, g_WTL);

    const int XN = S_LEN * D_MODEL;
    const int WN = D_MODEL * D_MODEL;

    bias_table_kernel<<<(NUM_HEADS * S_LEN + 255) / 256, 256>>>(rpe);

    int cgrid = XN / 4 / 256;
    convert_split_kernel<<<cgrid, 256>>>(query, xh,            xl);
    convert_split_kernel<<<cgrid, 256>>>(key,   xh + XN,       xl + XN);
    convert_split_kernel<<<cgrid, 256>>>(value, xh + 2 * XN,   xl + 2 * XN);
    dim3 wgrid(D_MODEL / 32, D_MODEL / 32);
    convert_wT_kernel<<<wgrid, 256>>>(Wq, wth,          wtl);
    convert_wT_kernel<<<wgrid, 256>>>(Wk, wth + WN,     wtl + WN);
    convert_wT_kernel<<<wgrid, 256>>>(Wv, wth + 2 * WN, wtl + 2 * WN);
    convert_wT_kernel<<<wgrid, 256>>>(Wo, wth + 3 * WN, wtl + 3 * WN);

    cudaFuncSetAttribute(gemm_bf16x3<true>,
                         cudaFuncAttributeMaxDynamicSharedMemorySize, GSMEM_BYTES);
    cudaFuncSetAttribute(gemm_bf16x3<false>,
                         cudaFuncAttributeMaxDynamicSharedMemorySize, GSMEM_BYTES);
    dim3 ggrid(D_MODEL / 128, S_LEN / 128);
    gemm_bf16x3<true><<<ggrid, 256, GSMEM_BYTES>>>(xh,          xl,          wth,          wtl,          bq, gQ);
    gemm_bf16x3<true><<<ggrid, 256, GSMEM_BYTES>>>(xh + XN,     xl + XN,     wth + WN,     wtl + WN,     bk, gK);
    gemm_bf16x3<true><<<ggrid, 256, GSMEM_BYTES>>>(xh + 2 * XN, xl + 2 * XN, wth + 2 * WN, wtl + 2 * WN, bv, gV);

    size_t fsmem = F_FLOATS * sizeof(float);
    cudaFuncSetAttribute(flash_mma_kernel, cudaFuncAttributeMaxDynamicSharedMemorySize,
                         (int)fsmem);
    dim3 fgrid(S_LEN / 128, NUM_HEADS);
    flash_mma_kernel<<<fgrid, 256, fsmem>>>(ch, cl);

    gemm_bf16x3<false><<<ggrid, 256, GSMEM_BYTES>>>(ch, cl, wth + 3 * WN, wtl + 3 * WN, bo, out);
    (void)in_sizes; (void)n_in; (void)out_size;
}